// round 15
// baseline (speedup 1.0000x reference)
#include <cuda_runtime.h>
#include <cuda_bf16.h>
#include <cstdint>

// ---------------- problem constants ----------------
#define BATCH 2
#define C 64
#define DW 128
#define HH 256
#define WW 256
#define HWPIX 65536
#define CELLS 64
#define TSU 40         // u32 row stride for bf16 weight tiles (40 % 32 == 8 -> LDS.64 conflict-free)
// per-cell demod weight scratch layout
#define W1OFF 0        // 128x64
#define W3OFF 8192     // 64x64
#define W4OFF 12288    // 128x64 (n2w-folded)
#define W5OFF 20480    // 64x64
#define AOFF  24576    // 128
#define BOFF  24704    // 128
#define PERCELL 24832

// ---------------- scratch ----------------
static __device__ float g_t[(size_t)BATCH * HWPIX * DW];     // channel-last
static __device__ float g_ymid[(size_t)BATCH * HWPIX * C];   // channel-last
static __device__ float g_sums[BATCH * CELLS * C];
static __device__ float g_wd[(size_t)BATCH * CELLS * PERCELL];

// ---------------- helpers ----------------
__device__ __forceinline__ uint32_t bfpack(float lo, float hi) {
    __nv_bfloat162 h = __floats2bfloat162_rn(lo, hi);
    return *reinterpret_cast<uint32_t*>(&h);
}
__device__ __forceinline__ void mma_bf16(float& d0, float& d1, float& d2, float& d3,
                                         uint32_t a0, uint32_t a1, uint32_t a2, uint32_t a3,
                                         uint32_t b0, uint32_t b1) {
    asm volatile(
        "mma.sync.aligned.m16n8k16.row.col.f32.bf16.bf16.f32 "
        "{%0,%1,%2,%3},{%4,%5,%6,%7},{%8,%9},{%0,%1,%2,%3};"
        : "+f"(d0), "+f"(d1), "+f"(d2), "+f"(d3)
        : "r"(a0), "r"(a1), "r"(a2), "r"(a3), "r"(b0), "r"(b1));
}
__device__ __forceinline__ float qsum(float v) {   // sum over quad (tig=0..3)
    v += __shfl_xor_sync(0xffffffffu, v, 1);
    v += __shfl_xor_sync(0xffffffffu, v, 2);
    return v;
}
// Stage fp32 weight rows [rows][64] into pair-permuted bf16 tiles:
// new u32 j in row o holds channels of old u32 m = (j>>3)*8 + ((j&7)>>1) + ((j&1)<<2)
// so the MMA's (k0, k0+4) pair is one LDS.64 at offset kt*8 + 2*tig.
__device__ __forceinline__ void stage_w(uint32_t* dst, const float* src,
                                        int rows, int tid, int nthr) {
    for (int i = tid; i < rows * 32; i += nthr) {
        const int o = i >> 5, j = i & 31;
        const int m = (j & ~7) + ((j & 7) >> 1) + ((j & 1) << 2);
        const int c = 2 * m;
        dst[o * TSU + j] = bfpack(src[o * 64 + c], src[o * 64 + c + 1]);
    }
}

// =====================================================================
// K0: demodulate all 1x1 conv weights once per (b, cell, output row).
// =====================================================================
__global__ __launch_bounds__(256) void k0_demod(
    const float* __restrict__ w1, const float* __restrict__ w3,
    const float* __restrict__ w4, const float* __restrict__ w5,
    const float* __restrict__ b4,
    const float* __restrict__ n2w, const float* __restrict__ n2b,
    const float* __restrict__ mod1, const float* __restrict__ mod3,
    const float* __restrict__ mod4, const float* __restrict__ mod5)
{
    __shared__ float tile[4096];
    __shared__ float psA[256];
    __shared__ float psB[256];
    __shared__ float ri[64];

    const int bid = blockIdx.x;
    const int b   = (bid >= 384) ? 1 : 0;
    const int rid = bid - 384 * b;
    const int tid = threadIdx.x;

    const float* wrow; const float* mblk; int dstoff; int isW4 = 0; int o;
    if (rid < 128)      { o = rid;       wrow = w1 + o * 64; mblk = mod1 + ((size_t)(b * 128 + o) << 12); dstoff = W1OFF + o * 64; }
    else if (rid < 192) { o = rid - 128; wrow = w3 + o * 64; mblk = mod3 + ((size_t)(b * 64  + o) << 12); dstoff = W3OFF + o * 64; }
    else if (rid < 320) { o = rid - 192; wrow = w4 + o * 64; mblk = mod4 + ((size_t)(b * 128 + o) << 12); dstoff = W4OFF + o * 64; isW4 = 1; }
    else                { o = rid - 320; wrow = w5 + o * 64; mblk = mod5 + ((size_t)(b * 64  + o) << 12); dstoff = W5OFF + o * 64; }

    for (int i = tid; i < 1024; i += 256)
        reinterpret_cast<float4*>(tile)[i] = reinterpret_cast<const float4*>(mblk)[i];
    __syncthreads();

    const int cell = tid & 63, part = tid >> 6;
    const int c0 = part * 16;
    float wv[16];
    float ss = 0.f;
    #pragma unroll
    for (int j = 0; j < 16; j++) {
        float t = wrow[c0 + j] * tile[(c0 + j) * 64 + cell];
        wv[j] = t; ss += t * t;
    }
    psA[part * 64 + cell] = ss;
    __syncthreads();
    if (tid < 64) ri[tid] = rsqrtf(psA[tid] + psA[64 + tid] + psA[128 + tid] + psA[192 + tid]);
    __syncthreads();
    const float r = ri[cell];
    float* dbase = g_wd + ((size_t)(b * 64 + cell)) * PERCELL + dstoff;

    if (!isW4) {
        #pragma unroll
        for (int j = 0; j < 16; j++) dbase[c0 + j] = wv[j] * r;
    } else {
        float aA = 0.f, bB = 0.f;
        #pragma unroll
        for (int j = 0; j < 16; j++) {
            float wd = wv[j] * r;
            float wn = wd * n2w[c0 + j];
            dbase[c0 + j] = wn;
            aA += wn;
            bB += wd * n2b[c0 + j];
        }
        psA[part * 64 + cell] = aA;
        psB[part * 64 + cell] = bB;
        __syncthreads();
        if (tid < 64) {
            float* cw = g_wd + ((size_t)(b * 64 + tid)) * PERCELL;
            cw[AOFF + o] = psA[tid] + psA[64 + tid] + psA[128 + tid] + psA[192 + tid];
            cw[BOFF + o] = psB[tid] + psB[64 + tid] + psB[128 + tid] + psB[192 + tid] + b4[o];
        }
    }
}

// =====================================================================
// K1 (bf16 mma, register-resident): LN1 + conv1x1 (64->128).
// grid=128, block=512; paired-weight LDS.64; no per-tile syncs.
// =====================================================================
#define K1_WB    0                         // 128*TSU u32
#define K1_B1    (K1_WB + 128*TSU*4)       // 128 f32
#define K1_N1W   (K1_B1 + 128*4)           // 64 f32
#define K1_N1B   (K1_N1W + 64*4)           // 64 f32
#define K1_SMEMB (K1_N1B + 64*4)

__global__ __launch_bounds__(512) void k1_tc(
    const float* __restrict__ x, const float* __restrict__ b1,
    const float* __restrict__ n1w, const float* __restrict__ n1b)
{
    extern __shared__ char smc[];
    uint32_t* Wb  = reinterpret_cast<uint32_t*>(smc + K1_WB);
    float* b1s  = reinterpret_cast<float*>(smc + K1_B1);
    float* n1ws = reinterpret_cast<float*>(smc + K1_N1W);
    float* n1bs = reinterpret_cast<float*>(smc + K1_N1B);

    const int tid = threadIdx.x;
    const int wid = tid >> 5, lane = tid & 31;
    const int g = lane >> 2, tig = lane & 3;
    const int cta = blockIdx.x;
    const int b = cta >> 6, cell = cta & 63;
    const int u = cell >> 3, v = cell & 7;

    const float* cellw = g_wd + ((size_t)(b * 64 + cell)) * PERCELL;
    stage_w(Wb, cellw + W1OFF, 128, tid, 512);
    if (tid < 128) b1s[tid] = b1[tid];
    if (tid < 64) { n1ws[tid] = n1w[tid]; n1bs[tid] = n1b[tid]; }
    __syncthreads();

    const size_t xbase = (size_t)b * C * HWPIX;
    const size_t tb2   = (size_t)b * HWPIX * DW;
    const int w16 = wid * 16;
    const int p0 = w16 + g, p1 = p0 + 8;

    #pragma unroll 1
    for (int t = 0; t < 4; t++) {
        const int pix0 = (u * 32 + t * 8) * WW + v * 32;
        const int gp0 = pix0 + ((p0 >> 5) << 8) + (p0 & 31);
        const int gp1 = pix0 + ((p1 >> 5) << 8) + (p1 & 31);

        // fragment-load x: 16 channels per thread per pixel row
        float xv0[16], xv1[16];
        #pragma unroll
        for (int kt = 0; kt < 4; kt++) {
            const int clo = 16 * kt + 2 * tig, chi = clo + 8;
            const float* xa = x + xbase + (size_t)clo * HWPIX;
            const float* xb = x + xbase + (size_t)chi * HWPIX;
            xv0[4 * kt]     = xa[gp0];          xv0[4 * kt + 1] = xa[HWPIX + gp0];
            xv0[4 * kt + 2] = xb[gp0];          xv0[4 * kt + 3] = xb[HWPIX + gp0];
            xv1[4 * kt]     = xa[gp1];          xv1[4 * kt + 1] = xa[HWPIX + gp1];
            xv1[4 * kt + 2] = xb[gp1];          xv1[4 * kt + 3] = xb[HWPIX + gp1];
        }

        // LN stats via quad reduction
        float s0 = 0.f, q0 = 0.f, s1 = 0.f, q1 = 0.f;
        #pragma unroll
        for (int i = 0; i < 16; i++) {
            s0 += xv0[i]; q0 += xv0[i] * xv0[i];
            s1 += xv1[i]; q1 += xv1[i] * xv1[i];
        }
        s0 = qsum(s0); q0 = qsum(q0); s1 = qsum(s1); q1 = qsum(q1);
        const float mu0 = s0 * (1.f / 64.f);
        const float rs0 = rsqrtf(q0 * (1.f / 64.f) - mu0 * mu0 + 1e-6f);
        const float mu1 = s1 * (1.f / 64.f);
        const float rs1 = rsqrtf(q1 * (1.f / 64.f) - mu1 * mu1 + 1e-6f);

        // GEMM
        float acc[64];
        #pragma unroll
        for (int i = 0; i < 64; i++) acc[i] = 0.f;
        #pragma unroll
        for (int kt = 0; kt < 4; kt++) {
            const int clo = 16 * kt + 2 * tig, chi = clo + 8;
            uint32_t a0 = bfpack((xv0[4 * kt]     - mu0) * rs0 * n1ws[clo]     + n1bs[clo],
                                 (xv0[4 * kt + 1] - mu0) * rs0 * n1ws[clo + 1] + n1bs[clo + 1]);
            uint32_t a1 = bfpack((xv1[4 * kt]     - mu1) * rs1 * n1ws[clo]     + n1bs[clo],
                                 (xv1[4 * kt + 1] - mu1) * rs1 * n1ws[clo + 1] + n1bs[clo + 1]);
            uint32_t a2 = bfpack((xv0[4 * kt + 2] - mu0) * rs0 * n1ws[chi]     + n1bs[chi],
                                 (xv0[4 * kt + 3] - mu0) * rs0 * n1ws[chi + 1] + n1bs[chi + 1]);
            uint32_t a3 = bfpack((xv1[4 * kt + 2] - mu1) * rs1 * n1ws[chi]     + n1bs[chi],
                                 (xv1[4 * kt + 3] - mu1) * rs1 * n1ws[chi + 1] + n1bs[chi + 1]);
            const int kb = kt * 8 + 2 * tig;
            #pragma unroll
            for (int nt = 0; nt < 16; nt++) {
                const uint2 bw = *reinterpret_cast<const uint2*>(Wb + (nt * 8 + g) * TSU + kb);
                mma_bf16(acc[nt * 4], acc[nt * 4 + 1], acc[nt * 4 + 2], acc[nt * 4 + 3],
                         a0, a1, a2, a3, bw.x, bw.y);
            }
        }

        // direct channel-last f32 store
        float* o0 = g_t + tb2 + (size_t)gp0 * DW;
        float* o1 = g_t + tb2 + (size_t)gp1 * DW;
        #pragma unroll
        for (int nt = 0; nt < 16; nt++) {
            const int o = nt * 8 + 2 * tig;
            *reinterpret_cast<float2*>(o0 + o) =
                make_float2(acc[nt * 4]     + b1s[o], acc[nt * 4 + 1] + b1s[o + 1]);
            *reinterpret_cast<float2*>(o1 + o) =
                make_float2(acc[nt * 4 + 2] + b1s[o], acc[nt * 4 + 3] + b1s[o + 1]);
        }
    }
}

// =====================================================================
// K2: depthwise 3x3 + SimpleGate + per-cell channel sums.
// Channel-last smem tile [1156][20] -> float4 STS/LDS, 16B-aligned rows.
// =====================================================================
#define K2T 20
#define K2_SMEMB (1156 * K2T * 4)
__global__ __launch_bounds__(256, 2) void k2_dw_gate(
    const float* __restrict__ w2, const float* __restrict__ b2,
    const float* __restrict__ mod2)
{
    extern __shared__ float tiles[];          // [1156][20]: a0..a7, g0..g7, pad4
    __shared__ float w2s[16 * 9];
    __shared__ float b2s[16];
    __shared__ float redbuf[64];

    const int bidx = blockIdx.x;
    const int b    = bidx >> 9;
    const int cell = (bidx >> 3) & 63;
    const int grp  = bidx & 7;
    const int u    = cell >> 3, v = cell & 7;
    const int tid  = threadIdx.x;
    const int cbase = grp * 8;

    if (tid < 16) {
        const int ch = (tid < 8) ? (cbase + tid) : (64 + cbase + tid - 8);
        const float m = mod2[(size_t)(b * DW + ch) * 64 + cell];
        float ss = 0.f;
        float wv[9];
        #pragma unroll
        for (int k = 0; k < 9; k++) { wv[k] = w2[ch * 9 + k] * m; ss += wv[k] * wv[k]; }
        const float rr = rsqrtf(ss);
        #pragma unroll
        for (int k = 0; k < 9; k++) w2s[tid * 9 + k] = wv[k] * rr;
        b2s[tid] = b2[ch];
    }
    __syncthreads();

    const size_t tb2 = (size_t)b * HWPIX * DW;
    const int h0 = u * 32 - 1, w0 = v * 32 - 1;

    for (int i = tid; i < 1156; i += 256) {
        const int ih = i / 34, iw = i - ih * 34;
        const int hh = h0 + ih, ww2 = w0 + iw;
        float4 qa0, qa1, qg0, qg1;
        if ((hh >= 0) & (hh < HH) & (ww2 >= 0) & (ww2 < WW)) {
            const float* bp = g_t + tb2 + (size_t)(hh * WW + ww2) * DW;
            qa0 = *reinterpret_cast<const float4*>(bp + cbase);
            qa1 = *reinterpret_cast<const float4*>(bp + cbase + 4);
            qg0 = *reinterpret_cast<const float4*>(bp + 64 + cbase);
            qg1 = *reinterpret_cast<const float4*>(bp + 64 + cbase + 4);
        } else {
            qa0 = qa1 = qg0 = qg1 = make_float4(0.f, 0.f, 0.f, 0.f);
        }
        float* tp = tiles + i * K2T;
        *reinterpret_cast<float4*>(tp)      = qa0;
        *reinterpret_cast<float4*>(tp + 4)  = qa1;
        *reinterpret_cast<float4*>(tp + 8)  = qg0;
        *reinterpret_cast<float4*>(tp + 12) = qg1;
    }
    __syncthreads();

    const int lane = tid & 31, warp = tid >> 5;
    const size_t ymb = (size_t)b * HWPIX * C;
    float csum[8];
    #pragma unroll
    for (int j = 0; j < 8; j++) csum[j] = 0.f;

    #pragma unroll
    for (int k = 0; k < 4; k++) {
        const int p = k * 256 + tid;
        const int ph = p >> 5, pw = p & 31;
        float av[8], gv[8];
        #pragma unroll
        for (int j = 0; j < 8; j++) { av[j] = b2s[j]; gv[j] = b2s[8 + j]; }
        #pragma unroll
        for (int dh = 0; dh < 3; dh++) {
            #pragma unroll
            for (int dw2 = 0; dw2 < 3; dw2++) {
                const float* tp = tiles + ((ph + dh) * 34 + pw + dw2) * K2T;
                const float4 a0 = *reinterpret_cast<const float4*>(tp);
                const float4 a1 = *reinterpret_cast<const float4*>(tp + 4);
                const float4 g0 = *reinterpret_cast<const float4*>(tp + 8);
                const float4 g1 = *reinterpret_cast<const float4*>(tp + 12);
                const int widx = dh * 3 + dw2;
                av[0] += w2s[0 * 9 + widx] * a0.x;  av[1] += w2s[1 * 9 + widx] * a0.y;
                av[2] += w2s[2 * 9 + widx] * a0.z;  av[3] += w2s[3 * 9 + widx] * a0.w;
                av[4] += w2s[4 * 9 + widx] * a1.x;  av[5] += w2s[5 * 9 + widx] * a1.y;
                av[6] += w2s[6 * 9 + widx] * a1.z;  av[7] += w2s[7 * 9 + widx] * a1.w;
                gv[0] += w2s[8 * 9 + widx] * g0.x;  gv[1] += w2s[9 * 9 + widx] * g0.y;
                gv[2] += w2s[10 * 9 + widx] * g0.z; gv[3] += w2s[11 * 9 + widx] * g0.w;
                gv[4] += w2s[12 * 9 + widx] * g1.x; gv[5] += w2s[13 * 9 + widx] * g1.y;
                gv[6] += w2s[14 * 9 + widx] * g1.z; gv[7] += w2s[15 * 9 + widx] * g1.w;
            }
        }
        float ov[8];
        #pragma unroll
        for (int j = 0; j < 8; j++) { ov[j] = av[j] * gv[j]; csum[j] += ov[j]; }
        float* yp = g_ymid + ymb + (size_t)((u * 32 + ph) * WW + v * 32 + pw) * C + cbase;
        *reinterpret_cast<float4*>(yp)     = make_float4(ov[0], ov[1], ov[2], ov[3]);
        *reinterpret_cast<float4*>(yp + 4) = make_float4(ov[4], ov[5], ov[6], ov[7]);
    }

    #pragma unroll
    for (int j = 0; j < 8; j++) {
        float ls = csum[j];
        for (int off = 16; off; off >>= 1) ls += __shfl_down_sync(0xffffffffu, ls, off);
        if (lane == 0) redbuf[j * 8 + warp] = ls;
    }
    __syncthreads();
    if (tid < 8) {
        float s = 0.f;
        #pragma unroll
        for (int i = 0; i < 8; i++) s += redbuf[tid * 8 + i];
        g_sums[((size_t)b * CELLS + cell) * C + cbase + tid] = s;
    }
}

// =====================================================================
// K4 (bf16 mma, register-resident chain):
// SCA -> conv3 -> y1(regs) -> LN2(quad shfl) -> conv4+gate(regs) -> conv5 -> out
// grid=128, block=512, paired-weight LDS.64, no per-tile syncs.
// =====================================================================
#define K4_W3B   0                          // 64*TSU u32
#define K4_W4B   (K4_W3B + 64*TSU*4)        // 128*TSU u32
#define K4_W5B   (K4_W4B + 128*TSU*4)       // 64*TSU u32
#define K4_SC1   (K4_W5B + 64*TSU*4)        // 256 f32 scratch
#define K4_SC2   (K4_SC1 + 256*4)           // 64 f32
#define K4_SSM   (K4_SC2 + 64*4)            // 64
#define K4_B3    (K4_SSM + 64*4)            // 64
#define K4_BE    (K4_B3 + 64*4)             // 64
#define K4_B5    (K4_BE + 64*4)             // 64
#define K4_GA    (K4_B5 + 64*4)             // 64
#define K4_AW    (K4_GA + 64*4)             // 128
#define K4_BW    (K4_AW + 128*4)            // 128
#define K4_SMEMB (K4_BW + 128*4)

__global__ __launch_bounds__(512) void k4_tc(
    const float* __restrict__ x,
    const float* __restrict__ b3, const float* __restrict__ b5,
    const float* __restrict__ beta, const float* __restrict__ gamma,
    const float* __restrict__ scaw, const float* __restrict__ scab,
    float* __restrict__ out)
{
    extern __shared__ char smc[];
    uint32_t* w3b = reinterpret_cast<uint32_t*>(smc + K4_W3B);
    uint32_t* w4b = reinterpret_cast<uint32_t*>(smc + K4_W4B);
    uint32_t* w5b = reinterpret_cast<uint32_t*>(smc + K4_W5B);
    float* sc1 = reinterpret_cast<float*>(smc + K4_SC1);
    float* sc2 = reinterpret_cast<float*>(smc + K4_SC2);
    float* ssm = reinterpret_cast<float*>(smc + K4_SSM);
    float* b3s = reinterpret_cast<float*>(smc + K4_B3);
    float* bes = reinterpret_cast<float*>(smc + K4_BE);
    float* b5s = reinterpret_cast<float*>(smc + K4_B5);
    float* gas = reinterpret_cast<float*>(smc + K4_GA);
    float* Aw  = reinterpret_cast<float*>(smc + K4_AW);
    float* Bw  = reinterpret_cast<float*>(smc + K4_BW);

    const int tid = threadIdx.x;
    const int wid = tid >> 5, lane = tid & 31;
    const int g = lane >> 2, tig = lane & 3;
    const int cta = blockIdx.x;
    const int b = cta >> 6, cell = cta & 63;
    const int u = cell >> 3, v = cell & 7;

    // ---- SCA in prologue ----
    if (tid < 256) {
        const int c = tid & 63, seg = tid >> 6;
        float s = 0.f;
        #pragma unroll 4
        for (int cl = seg * 16; cl < seg * 16 + 16; cl++)
            s += g_sums[((size_t)b * CELLS + cl) * C + c];
        sc1[tid] = s;
    }
    // ---- stage weights (paired bf16) ----
    const float* cellw = g_wd + ((size_t)(b * 64 + cell)) * PERCELL;
    stage_w(w3b, cellw + W3OFF, 64, tid, 512);
    stage_w(w4b, cellw + W4OFF, 128, tid, 512);
    stage_w(w5b, cellw + W5OFF, 64, tid, 512);
    if (tid < 64) {
        b3s[tid] = b3[tid];
        bes[tid] = beta[tid];
        b5s[tid] = b5[tid];
        gas[tid] = gamma[tid];
    }
    if (tid < 128) { Aw[tid] = cellw[AOFF + tid]; Bw[tid] = cellw[BOFF + tid]; }
    __syncthreads();
    if (tid < 64)
        sc2[tid] = (sc1[tid] + sc1[64 + tid] + sc1[128 + tid] + sc1[192 + tid]) * (1.f / (float)HWPIX);
    __syncthreads();
    if (tid < 64) {
        float acc = scab[tid];
        #pragma unroll 8
        for (int cc = 0; cc < 64; cc++) acc += scaw[tid * 64 + cc] * sc2[cc];
        ssm[tid] = acc;
    }
    __syncthreads();

    const size_t xbase = (size_t)b * C * HWPIX;
    const size_t ymb   = (size_t)b * HWPIX * C;
    const int w16 = wid * 16;
    const int p0 = w16 + g, p1 = p0 + 8;

    #pragma unroll 1
    for (int t = 0; t < 4; t++) {
        const int pix0 = (u * 32 + t * 8) * WW + v * 32;
        const int gp0 = pix0 + ((p0 >> 5) << 8) + (p0 & 31);
        const int gp1 = pix0 + ((p1 >> 5) << 8) + (p1 & 31);

        // ---- GEMM1: conv3 (N=64), A fragment-loaded from g_ymid ----
        float acc1[32];
        #pragma unroll
        for (int i = 0; i < 32; i++) acc1[i] = 0.f;
        #pragma unroll
        for (int kt = 0; kt < 4; kt++) {
            const int clo = 16 * kt + 2 * tig, chi = clo + 8;
            float2 l0 = *reinterpret_cast<const float2*>(g_ymid + ymb + (size_t)gp0 * C + clo);
            float2 l1 = *reinterpret_cast<const float2*>(g_ymid + ymb + (size_t)gp1 * C + clo);
            float2 h0 = *reinterpret_cast<const float2*>(g_ymid + ymb + (size_t)gp0 * C + chi);
            float2 h1 = *reinterpret_cast<const float2*>(g_ymid + ymb + (size_t)gp1 * C + chi);
            uint32_t a0 = bfpack(l0.x * ssm[clo], l0.y * ssm[clo + 1]);
            uint32_t a1 = bfpack(l1.x * ssm[clo], l1.y * ssm[clo + 1]);
            uint32_t a2 = bfpack(h0.x * ssm[chi], h0.y * ssm[chi + 1]);
            uint32_t a3 = bfpack(h1.x * ssm[chi], h1.y * ssm[chi + 1]);
            const int kb = kt * 8 + 2 * tig;
            #pragma unroll
            for (int nt = 0; nt < 8; nt++) {
                const uint2 bw = *reinterpret_cast<const uint2*>(w3b + (nt * 8 + g) * TSU + kb);
                mma_bf16(acc1[nt * 4], acc1[nt * 4 + 1], acc1[nt * 4 + 2], acc1[nt * 4 + 3],
                         a0, a1, a2, a3, bw.x, bw.y);
            }
        }

        // ---- y1 in registers ----
        float y0f[16], y1f[16];
        #pragma unroll
        for (int nt = 0; nt < 8; nt++) {
            const int c = nt * 8 + 2 * tig;
            const float* xp0 = x + xbase + (size_t)c * HWPIX;
            y0f[2 * nt]     = xp0[gp0]         + (acc1[nt * 4]     + b3s[c])     * bes[c];
            y0f[2 * nt + 1] = xp0[HWPIX + gp0] + (acc1[nt * 4 + 1] + b3s[c + 1]) * bes[c + 1];
            y1f[2 * nt]     = xp0[gp1]         + (acc1[nt * 4 + 2] + b3s[c])     * bes[c];
            y1f[2 * nt + 1] = xp0[HWPIX + gp1] + (acc1[nt * 4 + 3] + b3s[c + 1]) * bes[c + 1];
        }

        // ---- LN2 stats via quad reduction ----
        float s0 = 0.f, q0 = 0.f, s1 = 0.f, q1 = 0.f;
        #pragma unroll
        for (int i = 0; i < 16; i++) {
            s0 += y0f[i]; q0 += y0f[i] * y0f[i];
            s1 += y1f[i]; q1 += y1f[i] * y1f[i];
        }
        s0 = qsum(s0); q0 = qsum(q0); s1 = qsum(s1); q1 = qsum(q1);
        const float mu0 = s0 * (1.f / 64.f);
        const float rs0 = rsqrtf(q0 * (1.f / 64.f) - mu0 * mu0 + 1e-6f);
        const float mu1 = s1 * (1.f / 64.f);
        const float rs1 = rsqrtf(q1 * (1.f / 64.f) - mu1 * mu1 + 1e-6f);

        // ---- GEMM2: conv4 (N=128, LN folded), A from y1 registers ----
        float acc2[64];
        #pragma unroll
        for (int i = 0; i < 64; i++) acc2[i] = 0.f;
        #pragma unroll
        for (int kt = 0; kt < 4; kt++) {
            uint32_t a0 = bfpack(y0f[4 * kt],     y0f[4 * kt + 1]);
            uint32_t a1 = bfpack(y1f[4 * kt],     y1f[4 * kt + 1]);
            uint32_t a2 = bfpack(y0f[4 * kt + 2], y0f[4 * kt + 3]);
            uint32_t a3 = bfpack(y1f[4 * kt + 2], y1f[4 * kt + 3]);
            const int kb = kt * 8 + 2 * tig;
            #pragma unroll
            for (int nt = 0; nt < 16; nt++) {
                const uint2 bw = *reinterpret_cast<const uint2*>(w4b + (nt * 8 + g) * TSU + kb);
                mma_bf16(acc2[nt * 4], acc2[nt * 4 + 1], acc2[nt * 4 + 2], acc2[nt * 4 + 3],
                         a0, a1, a2, a3, bw.x, bw.y);
            }
        }

        // ---- gate -> zc registers ----
        float z0f[16], z1f[16];
        #pragma unroll
        for (int nt = 0; nt < 8; nt++) {
            const int c = nt * 8 + 2 * tig;
            float za00 = rs0 * (acc2[nt * 4]           - mu0 * Aw[c])      + Bw[c];
            float za01 = rs0 * (acc2[nt * 4 + 1]       - mu0 * Aw[c + 1])  + Bw[c + 1];
            float zg00 = rs0 * (acc2[(nt + 8) * 4]     - mu0 * Aw[c + 64]) + Bw[c + 64];
            float zg01 = rs0 * (acc2[(nt + 8) * 4 + 1] - mu0 * Aw[c + 65]) + Bw[c + 65];
            float za10 = rs1 * (acc2[nt * 4 + 2]       - mu1 * Aw[c])      + Bw[c];
            float za11 = rs1 * (acc2[nt * 4 + 3]       - mu1 * Aw[c + 1])  + Bw[c + 1];
            float zg10 = rs1 * (acc2[(nt + 8) * 4 + 2] - mu1 * Aw[c + 64]) + Bw[c + 64];
            float zg11 = rs1 * (acc2[(nt + 8) * 4 + 3] - mu1 * Aw[c + 65]) + Bw[c + 65];
            z0f[2 * nt]     = za00 * zg00;
            z0f[2 * nt + 1] = za01 * zg01;
            z1f[2 * nt]     = za10 * zg10;
            z1f[2 * nt + 1] = za11 * zg11;
        }

        // ---- GEMM3: conv5 (N=64), A from zc registers ----
        float acc3[32];
        #pragma unroll
        for (int i = 0; i < 32; i++) acc3[i] = 0.f;
        #pragma unroll
        for (int kt = 0; kt < 4; kt++) {
            uint32_t a0 = bfpack(z0f[4 * kt],     z0f[4 * kt + 1]);
            uint32_t a1 = bfpack(z1f[4 * kt],     z1f[4 * kt + 1]);
            uint32_t a2 = bfpack(z0f[4 * kt + 2], z0f[4 * kt + 3]);
            uint32_t a3 = bfpack(z1f[4 * kt + 2], z1f[4 * kt + 3]);
            const int kb = kt * 8 + 2 * tig;
            #pragma unroll
            for (int nt = 0; nt < 8; nt++) {
                const uint2 bw = *reinterpret_cast<const uint2*>(w5b + (nt * 8 + g) * TSU + kb);
                mma_bf16(acc3[nt * 4], acc3[nt * 4 + 1], acc3[nt * 4 + 2], acc3[nt * 4 + 3],
                         a0, a1, a2, a3, bw.x, bw.y);
            }
        }

        // ---- final epilogue (direct STG) ----
        #pragma unroll
        for (int nt = 0; nt < 8; nt++) {
            const int c = nt * 8 + 2 * tig;
            float* op0 = out + xbase + (size_t)c * HWPIX;
            op0[gp0]          = y0f[2 * nt]     + (acc3[nt * 4]     + b5s[c])     * gas[c];
            op0[HWPIX + gp0]  = y0f[2 * nt + 1] + (acc3[nt * 4 + 1] + b5s[c + 1]) * gas[c + 1];
            op0[gp1]          = y1f[2 * nt]     + (acc3[nt * 4 + 2] + b5s[c])     * gas[c];
            op0[HWPIX + gp1]  = y1f[2 * nt + 1] + (acc3[nt * 4 + 3] + b5s[c + 1]) * gas[c + 1];
        }
    }
}

// =====================================================================
// launch
// =====================================================================
extern "C" void kernel_launch(void* const* d_in, const int* in_sizes, int n_in,
                              void* d_out, int out_size)
{
    (void)in_sizes; (void)n_in; (void)out_size;
    const float* x     = (const float*)d_in[0];
    const float* w1    = (const float*)d_in[1];
    const float* b1    = (const float*)d_in[2];
    const float* w2    = (const float*)d_in[3];
    const float* b2    = (const float*)d_in[4];
    const float* w3    = (const float*)d_in[5];
    const float* b3    = (const float*)d_in[6];
    const float* scaw  = (const float*)d_in[7];
    const float* scab  = (const float*)d_in[8];
    const float* w4    = (const float*)d_in[9];
    const float* b4    = (const float*)d_in[10];
    const float* w5    = (const float*)d_in[11];
    const float* b5    = (const float*)d_in[12];
    const float* n1w   = (const float*)d_in[13];
    const float* n1b   = (const float*)d_in[14];
    const float* n2w   = (const float*)d_in[15];
    const float* n2b   = (const float*)d_in[16];
    const float* beta  = (const float*)d_in[17];
    const float* gamma = (const float*)d_in[18];
    const float* mod1  = (const float*)d_in[19];
    const float* mod2  = (const float*)d_in[20];
    const float* mod3  = (const float*)d_in[21];
    const float* mod4  = (const float*)d_in[22];
    const float* mod5  = (const float*)d_in[23];
    float* out = (float*)d_out;

    cudaFuncSetAttribute(k1_tc, cudaFuncAttributeMaxDynamicSharedMemorySize, K1_SMEMB);
    cudaFuncSetAttribute(k2_dw_gate, cudaFuncAttributeMaxDynamicSharedMemorySize, K2_SMEMB);
    cudaFuncSetAttribute(k4_tc, cudaFuncAttributeMaxDynamicSharedMemorySize, K4_SMEMB);

    k0_demod<<<2 * 384, 256>>>(w1, w3, w4, w5, b4, n2w, n2b, mod1, mod3, mod4, mod5);
    k1_tc<<<BATCH * CELLS, 512, K1_SMEMB>>>(x, b1, n1w, n1b);
    k2_dw_gate<<<1024, 256, K2_SMEMB>>>(w2, b2, mod2);
    k4_tc<<<BATCH * CELLS, 512, K4_SMEMB>>>(x, b3, b5, beta, gamma, scaw, scab, out);
}

// round 17
// speedup vs baseline: 1.0523x; 1.0523x over previous
#include <cuda_runtime.h>
#include <cuda_bf16.h>
#include <cstdint>

// ---------------- problem constants ----------------
#define BATCH 2
#define C 64
#define DW 128
#define HH 256
#define WW 256
#define HWPIX 65536
#define CELLS 64
#define TSU 40         // u32 row stride for bf16 weight tiles
// per-cell demod weight scratch layout
#define W1OFF 0        // 128x64
#define W3OFF 8192     // 64x64
#define W4OFF 12288    // 128x64 (n2w-folded)
#define W5OFF 20480    // 64x64
#define AOFF  24576    // 128
#define BOFF  24704    // 128
#define PERCELL 24832

// ---------------- scratch (bf16 intermediates: half the HBM traffic) ----------------
static __device__ __nv_bfloat16 g_t[(size_t)BATCH * HWPIX * DW];     // channel-last
static __device__ __nv_bfloat16 g_ymid[(size_t)BATCH * HWPIX * C];   // channel-last
static __device__ float g_sums[BATCH * CELLS * C];
static __device__ float g_wd[(size_t)BATCH * CELLS * PERCELL];

// ---------------- helpers ----------------
__device__ __forceinline__ uint32_t bfpack(float lo, float hi) {
    __nv_bfloat162 h = __floats2bfloat162_rn(lo, hi);
    return *reinterpret_cast<uint32_t*>(&h);
}
__device__ __forceinline__ float2 bfunp(uint32_t v) {
    return __bfloat1622float2(*reinterpret_cast<const __nv_bfloat162*>(&v));
}
__device__ __forceinline__ void mma_bf16(float& d0, float& d1, float& d2, float& d3,
                                         uint32_t a0, uint32_t a1, uint32_t a2, uint32_t a3,
                                         uint32_t b0, uint32_t b1) {
    asm volatile(
        "mma.sync.aligned.m16n8k16.row.col.f32.bf16.bf16.f32 "
        "{%0,%1,%2,%3},{%4,%5,%6,%7},{%8,%9},{%0,%1,%2,%3};"
        : "+f"(d0), "+f"(d1), "+f"(d2), "+f"(d3)
        : "r"(a0), "r"(a1), "r"(a2), "r"(a3), "r"(b0), "r"(b1));
}
__device__ __forceinline__ float qsum(float v) {   // sum over quad (tig=0..3)
    v += __shfl_xor_sync(0xffffffffu, v, 1);
    v += __shfl_xor_sync(0xffffffffu, v, 2);
    return v;
}
// Stage fp32 weight rows [rows][64] into pair-permuted bf16 tiles (LDS.64 pairs).
__device__ __forceinline__ void stage_w(uint32_t* dst, const float* src,
                                        int rows, int tid, int nthr) {
    for (int i = tid; i < rows * 32; i += nthr) {
        const int o = i >> 5, j = i & 31;
        const int m = (j & ~7) + ((j & 7) >> 1) + ((j & 1) << 2);
        const int c = 2 * m;
        dst[o * TSU + j] = bfpack(src[o * 64 + c], src[o * 64 + c + 1]);
    }
}

// =====================================================================
// K0: demodulate all 1x1 conv weights once per (b, cell, output row).
// =====================================================================
__global__ __launch_bounds__(256) void k0_demod(
    const float* __restrict__ w1, const float* __restrict__ w3,
    const float* __restrict__ w4, const float* __restrict__ w5,
    const float* __restrict__ b4,
    const float* __restrict__ n2w, const float* __restrict__ n2b,
    const float* __restrict__ mod1, const float* __restrict__ mod3,
    const float* __restrict__ mod4, const float* __restrict__ mod5)
{
    __shared__ float tile[4096];
    __shared__ float psA[256];
    __shared__ float psB[256];
    __shared__ float ri[64];

    const int bid = blockIdx.x;
    const int b   = (bid >= 384) ? 1 : 0;
    const int rid = bid - 384 * b;
    const int tid = threadIdx.x;

    const float* wrow; const float* mblk; int dstoff; int isW4 = 0; int o;
    if (rid < 128)      { o = rid;       wrow = w1 + o * 64; mblk = mod1 + ((size_t)(b * 128 + o) << 12); dstoff = W1OFF + o * 64; }
    else if (rid < 192) { o = rid - 128; wrow = w3 + o * 64; mblk = mod3 + ((size_t)(b * 64  + o) << 12); dstoff = W3OFF + o * 64; }
    else if (rid < 320) { o = rid - 192; wrow = w4 + o * 64; mblk = mod4 + ((size_t)(b * 128 + o) << 12); dstoff = W4OFF + o * 64; isW4 = 1; }
    else                { o = rid - 320; wrow = w5 + o * 64; mblk = mod5 + ((size_t)(b * 64  + o) << 12); dstoff = W5OFF + o * 64; }

    for (int i = tid; i < 1024; i += 256)
        reinterpret_cast<float4*>(tile)[i] = reinterpret_cast<const float4*>(mblk)[i];
    __syncthreads();

    const int cell = tid & 63, part = tid >> 6;
    const int c0 = part * 16;
    float wv[16];
    float ss = 0.f;
    #pragma unroll
    for (int j = 0; j < 16; j++) {
        float t = wrow[c0 + j] * tile[(c0 + j) * 64 + cell];
        wv[j] = t; ss += t * t;
    }
    psA[part * 64 + cell] = ss;
    __syncthreads();
    if (tid < 64) ri[tid] = rsqrtf(psA[tid] + psA[64 + tid] + psA[128 + tid] + psA[192 + tid]);
    __syncthreads();
    const float r = ri[cell];
    float* dbase = g_wd + ((size_t)(b * 64 + cell)) * PERCELL + dstoff;

    if (!isW4) {
        #pragma unroll
        for (int j = 0; j < 16; j++) dbase[c0 + j] = wv[j] * r;
    } else {
        float aA = 0.f, bB = 0.f;
        #pragma unroll
        for (int j = 0; j < 16; j++) {
            float wd = wv[j] * r;
            float wn = wd * n2w[c0 + j];
            dbase[c0 + j] = wn;
            aA += wn;
            bB += wd * n2b[c0 + j];
        }
        psA[part * 64 + cell] = aA;
        psB[part * 64 + cell] = bB;
        __syncthreads();
        if (tid < 64) {
            float* cw = g_wd + ((size_t)(b * 64 + tid)) * PERCELL;
            cw[AOFF + o] = psA[tid] + psA[64 + tid] + psA[128 + tid] + psA[192 + tid];
            cw[BOFF + o] = psB[tid] + psB[64 + tid] + psB[128 + tid] + psB[192 + tid] + b4[o];
        }
    }
}

// =====================================================================
// K1 (bf16 mma, register-resident): LN1 + conv1x1 (64->128).
// grid=128, block=512; bf16 channel-last stores to g_t.
// =====================================================================
#define K1_WB    0                         // 128*TSU u32
#define K1_B1    (K1_WB + 128*TSU*4)       // 128 f32
#define K1_N1W   (K1_B1 + 128*4)           // 64 f32
#define K1_N1B   (K1_N1W + 64*4)           // 64 f32
#define K1_SMEMB (K1_N1B + 64*4)

__global__ __launch_bounds__(512) void k1_tc(
    const float* __restrict__ x, const float* __restrict__ b1,
    const float* __restrict__ n1w, const float* __restrict__ n1b)
{
    extern __shared__ char smc[];
    uint32_t* Wb  = reinterpret_cast<uint32_t*>(smc + K1_WB);
    float* b1s  = reinterpret_cast<float*>(smc + K1_B1);
    float* n1ws = reinterpret_cast<float*>(smc + K1_N1W);
    float* n1bs = reinterpret_cast<float*>(smc + K1_N1B);

    const int tid = threadIdx.x;
    const int wid = tid >> 5, lane = tid & 31;
    const int g = lane >> 2, tig = lane & 3;
    const int cta = blockIdx.x;
    const int b = cta >> 6, cell = cta & 63;
    const int u = cell >> 3, v = cell & 7;

    const float* cellw = g_wd + ((size_t)(b * 64 + cell)) * PERCELL;
    stage_w(Wb, cellw + W1OFF, 128, tid, 512);
    if (tid < 128) b1s[tid] = b1[tid];
    if (tid < 64) { n1ws[tid] = n1w[tid]; n1bs[tid] = n1b[tid]; }
    __syncthreads();

    const size_t xbase = (size_t)b * C * HWPIX;
    const size_t tb2   = (size_t)b * HWPIX * DW;
    const int w16 = wid * 16;
    const int p0 = w16 + g, p1 = p0 + 8;

    #pragma unroll 1
    for (int t = 0; t < 4; t++) {
        const int pix0 = (u * 32 + t * 8) * WW + v * 32;
        const int gp0 = pix0 + ((p0 >> 5) << 8) + (p0 & 31);
        const int gp1 = pix0 + ((p1 >> 5) << 8) + (p1 & 31);

        // fragment-load x: 16 channels per thread per pixel row
        float xv0[16], xv1[16];
        #pragma unroll
        for (int kt = 0; kt < 4; kt++) {
            const int clo = 16 * kt + 2 * tig, chi = clo + 8;
            const float* xa = x + xbase + (size_t)clo * HWPIX;
            const float* xb = x + xbase + (size_t)chi * HWPIX;
            xv0[4 * kt]     = xa[gp0];          xv0[4 * kt + 1] = xa[HWPIX + gp0];
            xv0[4 * kt + 2] = xb[gp0];          xv0[4 * kt + 3] = xb[HWPIX + gp0];
            xv1[4 * kt]     = xa[gp1];          xv1[4 * kt + 1] = xa[HWPIX + gp1];
            xv1[4 * kt + 2] = xb[gp1];          xv1[4 * kt + 3] = xb[HWPIX + gp1];
        }

        // LN stats via quad reduction
        float s0 = 0.f, q0 = 0.f, s1 = 0.f, q1 = 0.f;
        #pragma unroll
        for (int i = 0; i < 16; i++) {
            s0 += xv0[i]; q0 += xv0[i] * xv0[i];
            s1 += xv1[i]; q1 += xv1[i] * xv1[i];
        }
        s0 = qsum(s0); q0 = qsum(q0); s1 = qsum(s1); q1 = qsum(q1);
        const float mu0 = s0 * (1.f / 64.f);
        const float rs0 = rsqrtf(q0 * (1.f / 64.f) - mu0 * mu0 + 1e-6f);
        const float mu1 = s1 * (1.f / 64.f);
        const float rs1 = rsqrtf(q1 * (1.f / 64.f) - mu1 * mu1 + 1e-6f);

        // GEMM
        float acc[64];
        #pragma unroll
        for (int i = 0; i < 64; i++) acc[i] = 0.f;
        #pragma unroll
        for (int kt = 0; kt < 4; kt++) {
            const int clo = 16 * kt + 2 * tig, chi = clo + 8;
            uint32_t a0 = bfpack((xv0[4 * kt]     - mu0) * rs0 * n1ws[clo]     + n1bs[clo],
                                 (xv0[4 * kt + 1] - mu0) * rs0 * n1ws[clo + 1] + n1bs[clo + 1]);
            uint32_t a1 = bfpack((xv1[4 * kt]     - mu1) * rs1 * n1ws[clo]     + n1bs[clo],
                                 (xv1[4 * kt + 1] - mu1) * rs1 * n1ws[clo + 1] + n1bs[clo + 1]);
            uint32_t a2 = bfpack((xv0[4 * kt + 2] - mu0) * rs0 * n1ws[chi]     + n1bs[chi],
                                 (xv0[4 * kt + 3] - mu0) * rs0 * n1ws[chi + 1] + n1bs[chi + 1]);
            uint32_t a3 = bfpack((xv1[4 * kt + 2] - mu1) * rs1 * n1ws[chi]     + n1bs[chi],
                                 (xv1[4 * kt + 3] - mu1) * rs1 * n1ws[chi + 1] + n1bs[chi + 1]);
            const int kb = kt * 8 + 2 * tig;
            #pragma unroll
            for (int nt = 0; nt < 16; nt++) {
                const uint2 bw = *reinterpret_cast<const uint2*>(Wb + (nt * 8 + g) * TSU + kb);
                mma_bf16(acc[nt * 4], acc[nt * 4 + 1], acc[nt * 4 + 2], acc[nt * 4 + 3],
                         a0, a1, a2, a3, bw.x, bw.y);
            }
        }

        // direct channel-last bf16 store (2 channels = one u32)
        uint32_t* o0 = reinterpret_cast<uint32_t*>(g_t + tb2 + (size_t)gp0 * DW);
        uint32_t* o1 = reinterpret_cast<uint32_t*>(g_t + tb2 + (size_t)gp1 * DW);
        #pragma unroll
        for (int nt = 0; nt < 16; nt++) {
            const int o = nt * 8 + 2 * tig;
            o0[o >> 1] = bfpack(acc[nt * 4]     + b1s[o], acc[nt * 4 + 1] + b1s[o + 1]);
            o1[o >> 1] = bfpack(acc[nt * 4 + 2] + b1s[o], acc[nt * 4 + 3] + b1s[o + 1]);
        }
    }
}

// =====================================================================
// K2: depthwise 3x3 + SimpleGate + per-cell channel sums.
// bf16 global IO (uint4 = 8 channels); f32 smem tile [1156][20].
// =====================================================================
#define K2T 20
#define K2_SMEMB (1156 * K2T * 4)
__global__ __launch_bounds__(256, 2) void k2_dw_gate(
    const float* __restrict__ w2, const float* __restrict__ b2,
    const float* __restrict__ mod2)
{
    extern __shared__ float tiles[];          // [1156][20]: a0..a7, g0..g7, pad4
    __shared__ float w2s[16 * 9];
    __shared__ float b2s[16];
    __shared__ float redbuf[64];

    const int bidx = blockIdx.x;
    const int b    = bidx >> 9;
    const int cell = (bidx >> 3) & 63;
    const int grp  = bidx & 7;
    const int u    = cell >> 3, v = cell & 7;
    const int tid  = threadIdx.x;
    const int cbase = grp * 8;

    if (tid < 16) {
        const int ch = (tid < 8) ? (cbase + tid) : (64 + cbase + tid - 8);
        const float m = mod2[(size_t)(b * DW + ch) * 64 + cell];
        float ss = 0.f;
        float wv[9];
        #pragma unroll
        for (int k = 0; k < 9; k++) { wv[k] = w2[ch * 9 + k] * m; ss += wv[k] * wv[k]; }
        const float rr = rsqrtf(ss);
        #pragma unroll
        for (int k = 0; k < 9; k++) w2s[tid * 9 + k] = wv[k] * rr;
        b2s[tid] = b2[ch];
    }
    __syncthreads();

    const size_t tb2 = (size_t)b * HWPIX * DW;
    const int h0 = u * 32 - 1, w0 = v * 32 - 1;

    for (int i = tid; i < 1156; i += 256) {
        const int ih = i / 34, iw = i - ih * 34;
        const int hh = h0 + ih, ww2 = w0 + iw;
        float* tp = tiles + i * K2T;
        if ((hh >= 0) & (hh < HH) & (ww2 >= 0) & (ww2 < WW)) {
            const __nv_bfloat16* bp = g_t + tb2 + (size_t)(hh * WW + ww2) * DW;
            uint4 qa = *reinterpret_cast<const uint4*>(bp + cbase);
            uint4 qg = *reinterpret_cast<const uint4*>(bp + 64 + cbase);
            float2 f;
            f = bfunp(qa.x); tp[0] = f.x;  tp[1] = f.y;
            f = bfunp(qa.y); tp[2] = f.x;  tp[3] = f.y;
            f = bfunp(qa.z); tp[4] = f.x;  tp[5] = f.y;
            f = bfunp(qa.w); tp[6] = f.x;  tp[7] = f.y;
            f = bfunp(qg.x); tp[8] = f.x;  tp[9] = f.y;
            f = bfunp(qg.y); tp[10] = f.x; tp[11] = f.y;
            f = bfunp(qg.z); tp[12] = f.x; tp[13] = f.y;
            f = bfunp(qg.w); tp[14] = f.x; tp[15] = f.y;
        } else {
            const float4 z = make_float4(0.f, 0.f, 0.f, 0.f);
            *reinterpret_cast<float4*>(tp)      = z;
            *reinterpret_cast<float4*>(tp + 4)  = z;
            *reinterpret_cast<float4*>(tp + 8)  = z;
            *reinterpret_cast<float4*>(tp + 12) = z;
        }
    }
    __syncthreads();

    const int lane = tid & 31, warp = tid >> 5;
    const size_t ymb = (size_t)b * HWPIX * C;
    float csum[8];
    #pragma unroll
    for (int j = 0; j < 8; j++) csum[j] = 0.f;

    #pragma unroll
    for (int k = 0; k < 4; k++) {
        const int p = k * 256 + tid;
        const int ph = p >> 5, pw = p & 31;
        float av[8], gv[8];
        #pragma unroll
        for (int j = 0; j < 8; j++) { av[j] = b2s[j]; gv[j] = b2s[8 + j]; }
        #pragma unroll
        for (int dh = 0; dh < 3; dh++) {
            #pragma unroll
            for (int dw2 = 0; dw2 < 3; dw2++) {
                const float* tp = tiles + ((ph + dh) * 34 + pw + dw2) * K2T;
                const float4 a0 = *reinterpret_cast<const float4*>(tp);
                const float4 a1 = *reinterpret_cast<const float4*>(tp + 4);
                const float4 g0 = *reinterpret_cast<const float4*>(tp + 8);
                const float4 g1 = *reinterpret_cast<const float4*>(tp + 12);
                const int widx = dh * 3 + dw2;
                av[0] += w2s[0 * 9 + widx] * a0.x;  av[1] += w2s[1 * 9 + widx] * a0.y;
                av[2] += w2s[2 * 9 + widx] * a0.z;  av[3] += w2s[3 * 9 + widx] * a0.w;
                av[4] += w2s[4 * 9 + widx] * a1.x;  av[5] += w2s[5 * 9 + widx] * a1.y;
                av[6] += w2s[6 * 9 + widx] * a1.z;  av[7] += w2s[7 * 9 + widx] * a1.w;
                gv[0] += w2s[8 * 9 + widx] * g0.x;  gv[1] += w2s[9 * 9 + widx] * g0.y;
                gv[2] += w2s[10 * 9 + widx] * g0.z; gv[3] += w2s[11 * 9 + widx] * g0.w;
                gv[4] += w2s[12 * 9 + widx] * g1.x; gv[5] += w2s[13 * 9 + widx] * g1.y;
                gv[6] += w2s[14 * 9 + widx] * g1.z; gv[7] += w2s[15 * 9 + widx] * g1.w;
            }
        }
        float ov[8];
        #pragma unroll
        for (int j = 0; j < 8; j++) { ov[j] = av[j] * gv[j]; csum[j] += ov[j]; }
        __nv_bfloat16* yp = g_ymid + ymb + (size_t)((u * 32 + ph) * WW + v * 32 + pw) * C + cbase;
        *reinterpret_cast<uint4*>(yp) = make_uint4(
            bfpack(ov[0], ov[1]), bfpack(ov[2], ov[3]),
            bfpack(ov[4], ov[5]), bfpack(ov[6], ov[7]));
    }

    #pragma unroll
    for (int j = 0; j < 8; j++) {
        float ls = csum[j];
        for (int off = 16; off; off >>= 1) ls += __shfl_down_sync(0xffffffffu, ls, off);
        if (lane == 0) redbuf[j * 8 + warp] = ls;
    }
    __syncthreads();
    if (tid < 8) {
        float s = 0.f;
        #pragma unroll
        for (int i = 0; i < 8; i++) s += redbuf[tid * 8 + i];
        g_sums[((size_t)b * CELLS + cell) * C + cbase + tid] = s;
    }
}

// =====================================================================
// K4 (bf16 mma, register-resident chain):
// SCA -> conv3 -> y1(regs) -> LN2(quad shfl) -> conv4+gate(regs) -> conv5 -> out
// grid=128, block=512. bf16 g_ymid loads.
// =====================================================================
#define K4_W3B   0                          // 64*TSU u32
#define K4_W4B   (K4_W3B + 64*TSU*4)        // 128*TSU u32
#define K4_W5B   (K4_W4B + 128*TSU*4)       // 64*TSU u32
#define K4_SC1   (K4_W5B + 64*TSU*4)        // 256 f32 scratch
#define K4_SC2   (K4_SC1 + 256*4)           // 64 f32
#define K4_SSM   (K4_SC2 + 64*4)            // 64
#define K4_B3    (K4_SSM + 64*4)            // 64
#define K4_BE    (K4_B3 + 64*4)             // 64
#define K4_B5    (K4_BE + 64*4)             // 64
#define K4_GA    (K4_B5 + 64*4)             // 64
#define K4_AW    (K4_GA + 64*4)             // 128
#define K4_BW    (K4_AW + 128*4)            // 128
#define K4_SMEMB (K4_BW + 128*4)

__global__ __launch_bounds__(512) void k4_tc(
    const float* __restrict__ x,
    const float* __restrict__ b3, const float* __restrict__ b5,
    const float* __restrict__ beta, const float* __restrict__ gamma,
    const float* __restrict__ scaw, const float* __restrict__ scab,
    float* __restrict__ out)
{
    extern __shared__ char smc[];
    uint32_t* w3b = reinterpret_cast<uint32_t*>(smc + K4_W3B);
    uint32_t* w4b = reinterpret_cast<uint32_t*>(smc + K4_W4B);
    uint32_t* w5b = reinterpret_cast<uint32_t*>(smc + K4_W5B);
    float* sc1 = reinterpret_cast<float*>(smc + K4_SC1);
    float* sc2 = reinterpret_cast<float*>(smc + K4_SC2);
    float* ssm = reinterpret_cast<float*>(smc + K4_SSM);
    float* b3s = reinterpret_cast<float*>(smc + K4_B3);
    float* bes = reinterpret_cast<float*>(smc + K4_BE);
    float* b5s = reinterpret_cast<float*>(smc + K4_B5);
    float* gas = reinterpret_cast<float*>(smc + K4_GA);
    float* Aw  = reinterpret_cast<float*>(smc + K4_AW);
    float* Bw  = reinterpret_cast<float*>(smc + K4_BW);

    const int tid = threadIdx.x;
    const int wid = tid >> 5, lane = tid & 31;
    const int g = lane >> 2, tig = lane & 3;
    const int cta = blockIdx.x;
    const int b = cta >> 6, cell = cta & 63;
    const int u = cell >> 3, v = cell & 7;

    // ---- SCA in prologue ----
    if (tid < 256) {
        const int c = tid & 63, seg = tid >> 6;
        float s = 0.f;
        #pragma unroll 4
        for (int cl = seg * 16; cl < seg * 16 + 16; cl++)
            s += g_sums[((size_t)b * CELLS + cl) * C + c];
        sc1[tid] = s;
    }
    // ---- stage weights (paired bf16) ----
    const float* cellw = g_wd + ((size_t)(b * 64 + cell)) * PERCELL;
    stage_w(w3b, cellw + W3OFF, 64, tid, 512);
    stage_w(w4b, cellw + W4OFF, 128, tid, 512);
    stage_w(w5b, cellw + W5OFF, 64, tid, 512);
    if (tid < 64) {
        b3s[tid] = b3[tid];
        bes[tid] = beta[tid];
        b5s[tid] = b5[tid];
        gas[tid] = gamma[tid];
    }
    if (tid < 128) { Aw[tid] = cellw[AOFF + tid]; Bw[tid] = cellw[BOFF + tid]; }
    __syncthreads();
    if (tid < 64)
        sc2[tid] = (sc1[tid] + sc1[64 + tid] + sc1[128 + tid] + sc1[192 + tid]) * (1.f / (float)HWPIX);
    __syncthreads();
    if (tid < 64) {
        float acc = scab[tid];
        #pragma unroll 8
        for (int cc = 0; cc < 64; cc++) acc += scaw[tid * 64 + cc] * sc2[cc];
        ssm[tid] = acc;
    }
    __syncthreads();

    const size_t xbase = (size_t)b * C * HWPIX;
    const size_t ymb   = (size_t)b * HWPIX * C;
    const int w16 = wid * 16;
    const int p0 = w16 + g, p1 = p0 + 8;

    #pragma unroll 1
    for (int t = 0; t < 4; t++) {
        const int pix0 = (u * 32 + t * 8) * WW + v * 32;
        const int gp0 = pix0 + ((p0 >> 5) << 8) + (p0 & 31);
        const int gp1 = pix0 + ((p1 >> 5) << 8) + (p1 & 31);

        // ---- GEMM1: conv3 (N=64), A fragment-loaded from bf16 g_ymid ----
        float acc1[32];
        #pragma unroll
        for (int i = 0; i < 32; i++) acc1[i] = 0.f;
        const uint32_t* yb0 = reinterpret_cast<const uint32_t*>(g_ymid + ymb + (size_t)gp0 * C);
        const uint32_t* yb1 = reinterpret_cast<const uint32_t*>(g_ymid + ymb + (size_t)gp1 * C);
        #pragma unroll
        for (int kt = 0; kt < 4; kt++) {
            const int clo = 16 * kt + 2 * tig, chi = clo + 8;
            float2 l0 = bfunp(yb0[clo >> 1]);
            float2 l1 = bfunp(yb1[clo >> 1]);
            float2 h0 = bfunp(yb0[chi >> 1]);
            float2 h1 = bfunp(yb1[chi >> 1]);
            uint32_t a0 = bfpack(l0.x * ssm[clo], l0.y * ssm[clo + 1]);
            uint32_t a1 = bfpack(l1.x * ssm[clo], l1.y * ssm[clo + 1]);
            uint32_t a2 = bfpack(h0.x * ssm[chi], h0.y * ssm[chi + 1]);
            uint32_t a3 = bfpack(h1.x * ssm[chi], h1.y * ssm[chi + 1]);
            const int kb = kt * 8 + 2 * tig;
            #pragma unroll
            for (int nt = 0; nt < 8; nt++) {
                const uint2 bw = *reinterpret_cast<const uint2*>(w3b + (nt * 8 + g) * TSU + kb);
                mma_bf16(acc1[nt * 4], acc1[nt * 4 + 1], acc1[nt * 4 + 2], acc1[nt * 4 + 3],
                         a0, a1, a2, a3, bw.x, bw.y);
            }
        }

        // ---- y1 in registers ----
        float y0f[16], y1f[16];
        #pragma unroll
        for (int nt = 0; nt < 8; nt++) {
            const int c = nt * 8 + 2 * tig;
            const float* xp0 = x + xbase + (size_t)c * HWPIX;
            y0f[2 * nt]     = xp0[gp0]         + (acc1[nt * 4]     + b3s[c])     * bes[c];
            y0f[2 * nt + 1] = xp0[HWPIX + gp0] + (acc1[nt * 4 + 1] + b3s[c + 1]) * bes[c + 1];
            y1f[2 * nt]     = xp0[gp1]         + (acc1[nt * 4 + 2] + b3s[c])     * bes[c];
            y1f[2 * nt + 1] = xp0[HWPIX + gp1] + (acc1[nt * 4 + 3] + b3s[c + 1]) * bes[c + 1];
        }

        // ---- LN2 stats via quad reduction ----
        float s0 = 0.f, q0 = 0.f, s1 = 0.f, q1 = 0.f;
        #pragma unroll
        for (int i = 0; i < 16; i++) {
            s0 += y0f[i]; q0 += y0f[i] * y0f[i];
            s1 += y1f[i]; q1 += y1f[i] * y1f[i];
        }
        s0 = qsum(s0); q0 = qsum(q0); s1 = qsum(s1); q1 = qsum(q1);
        const float mu0 = s0 * (1.f / 64.f);
        const float rs0 = rsqrtf(q0 * (1.f / 64.f) - mu0 * mu0 + 1e-6f);
        const float mu1 = s1 * (1.f / 64.f);
        const float rs1 = rsqrtf(q1 * (1.f / 64.f) - mu1 * mu1 + 1e-6f);

        // ---- GEMM2: conv4 (N=128, LN folded), A from y1 registers ----
        float acc2[64];
        #pragma unroll
        for (int i = 0; i < 64; i++) acc2[i] = 0.f;
        #pragma unroll
        for (int kt = 0; kt < 4; kt++) {
            uint32_t a0 = bfpack(y0f[4 * kt],     y0f[4 * kt + 1]);
            uint32_t a1 = bfpack(y1f[4 * kt],     y1f[4 * kt + 1]);
            uint32_t a2 = bfpack(y0f[4 * kt + 2], y0f[4 * kt + 3]);
            uint32_t a3 = bfpack(y1f[4 * kt + 2], y1f[4 * kt + 3]);
            const int kb = kt * 8 + 2 * tig;
            #pragma unroll
            for (int nt = 0; nt < 16; nt++) {
                const uint2 bw = *reinterpret_cast<const uint2*>(w4b + (nt * 8 + g) * TSU + kb);
                mma_bf16(acc2[nt * 4], acc2[nt * 4 + 1], acc2[nt * 4 + 2], acc2[nt * 4 + 3],
                         a0, a1, a2, a3, bw.x, bw.y);
            }
        }

        // ---- gate -> zc registers ----
        float z0f[16], z1f[16];
        #pragma unroll
        for (int nt = 0; nt < 8; nt++) {
            const int c = nt * 8 + 2 * tig;
            float za00 = rs0 * (acc2[nt * 4]           - mu0 * Aw[c])      + Bw[c];
            float za01 = rs0 * (acc2[nt * 4 + 1]       - mu0 * Aw[c + 1])  + Bw[c + 1];
            float zg00 = rs0 * (acc2[(nt + 8) * 4]     - mu0 * Aw[c + 64]) + Bw[c + 64];
            float zg01 = rs0 * (acc2[(nt + 8) * 4 + 1] - mu0 * Aw[c + 65]) + Bw[c + 65];
            float za10 = rs1 * (acc2[nt * 4 + 2]       - mu1 * Aw[c])      + Bw[c];
            float za11 = rs1 * (acc2[nt * 4 + 3]       - mu1 * Aw[c + 1])  + Bw[c + 1];
            float zg10 = rs1 * (acc2[(nt + 8) * 4 + 2] - mu1 * Aw[c + 64]) + Bw[c + 64];
            float zg11 = rs1 * (acc2[(nt + 8) * 4 + 3] - mu1 * Aw[c + 65]) + Bw[c + 65];
            z0f[2 * nt]     = za00 * zg00;
            z0f[2 * nt + 1] = za01 * zg01;
            z1f[2 * nt]     = za10 * zg10;
            z1f[2 * nt + 1] = za11 * zg11;
        }

        // ---- GEMM3: conv5 (N=64), A from zc registers ----
        float acc3[32];
        #pragma unroll
        for (int i = 0; i < 32; i++) acc3[i] = 0.f;
        #pragma unroll
        for (int kt = 0; kt < 4; kt++) {
            uint32_t a0 = bfpack(z0f[4 * kt],     z0f[4 * kt + 1]);
            uint32_t a1 = bfpack(z1f[4 * kt],     z1f[4 * kt + 1]);
            uint32_t a2 = bfpack(z0f[4 * kt + 2], z0f[4 * kt + 3]);
            uint32_t a3 = bfpack(z1f[4 * kt + 2], z1f[4 * kt + 3]);
            const int kb = kt * 8 + 2 * tig;
            #pragma unroll
            for (int nt = 0; nt < 8; nt++) {
                const uint2 bw = *reinterpret_cast<const uint2*>(w5b + (nt * 8 + g) * TSU + kb);
                mma_bf16(acc3[nt * 4], acc3[nt * 4 + 1], acc3[nt * 4 + 2], acc3[nt * 4 + 3],
                         a0, a1, a2, a3, bw.x, bw.y);
            }
        }

        // ---- final epilogue (direct STG) ----
        #pragma unroll
        for (int nt = 0; nt < 8; nt++) {
            const int c = nt * 8 + 2 * tig;
            float* op0 = out + xbase + (size_t)c * HWPIX;
            op0[gp0]          = y0f[2 * nt]     + (acc3[nt * 4]     + b5s[c])     * gas[c];
            op0[HWPIX + gp0]  = y0f[2 * nt + 1] + (acc3[nt * 4 + 1] + b5s[c + 1]) * gas[c + 1];
            op0[gp1]          = y1f[2 * nt]     + (acc3[nt * 4 + 2] + b5s[c])     * gas[c];
            op0[HWPIX + gp1]  = y1f[2 * nt + 1] + (acc3[nt * 4 + 3] + b5s[c + 1]) * gas[c + 1];
        }
    }
}

// =====================================================================
// launch
// =====================================================================
extern "C" void kernel_launch(void* const* d_in, const int* in_sizes, int n_in,
                              void* d_out, int out_size)
{
    (void)in_sizes; (void)n_in; (void)out_size;
    const float* x     = (const float*)d_in[0];
    const float* w1    = (const float*)d_in[1];
    const float* b1    = (const float*)d_in[2];
    const float* w2    = (const float*)d_in[3];
    const float* b2    = (const float*)d_in[4];
    const float* w3    = (const float*)d_in[5];
    const float* b3    = (const float*)d_in[6];
    const float* scaw  = (const float*)d_in[7];
    const float* scab  = (const float*)d_in[8];
    const float* w4    = (const float*)d_in[9];
    const float* b4    = (const float*)d_in[10];
    const float* w5    = (const float*)d_in[11];
    const float* b5    = (const float*)d_in[12];
    const float* n1w   = (const float*)d_in[13];
    const float* n1b   = (const float*)d_in[14];
    const float* n2w   = (const float*)d_in[15];
    const float* n2b   = (const float*)d_in[16];
    const float* beta  = (const float*)d_in[17];
    const float* gamma = (const float*)d_in[18];
    const float* mod1  = (const float*)d_in[19];
    const float* mod2  = (const float*)d_in[20];
    const float* mod3  = (const float*)d_in[21];
    const float* mod4  = (const float*)d_in[22];
    const float* mod5  = (const float*)d_in[23];
    float* out = (float*)d_out;

    cudaFuncSetAttribute(k1_tc, cudaFuncAttributeMaxDynamicSharedMemorySize, K1_SMEMB);
    cudaFuncSetAttribute(k2_dw_gate, cudaFuncAttributeMaxDynamicSharedMemorySize, K2_SMEMB);
    cudaFuncSetAttribute(k4_tc, cudaFuncAttributeMaxDynamicSharedMemorySize, K4_SMEMB);

    k0_demod<<<2 * 384, 256>>>(w1, w3, w4, w5, b4, n2w, n2b, mod1, mod3, mod4, mod5);
    k1_tc<<<BATCH * CELLS, 512, K1_SMEMB>>>(x, b1, n1w, n1b);
    k2_dw_gate<<<1024, 256, K2_SMEMB>>>(w2, b2, mod2);
    k4_tc<<<BATCH * CELLS, 512, K4_SMEMB>>>(x, b3, b5, beta, gamma, scaw, scab, out);
}